// round 16
// baseline (speedup 1.0000x reference)
#include <cuda_runtime.h>
#include <cuda_bf16.h>
#include <math.h>
#include <cstdint>

#define NN 4096
#define DD 64
#define HH 4
#define NSTEPS 4
#define NW (NN/32)   // 128 mask words per row

// ---------------- scratch (__device__ globals; no allocations) ----------------
__device__ __nv_bfloat16  g_hnhi[(size_t)HH * NN * DD];   // normalized hn bf16 hi
__device__ __nv_bfloat16  g_hnlo[(size_t)HH * NN * DD];   // normalized hn bf16 lo
__device__ __nv_bfloat16  g_hbhi[(size_t)HH * NN * DD];   // h bf16 hi
__device__ __nv_bfloat16  g_hblo[(size_t)HH * NN * DD];   // h bf16 lo
__device__ unsigned       g_rowmax[HH * NN];
__device__ float          g_hmean [HH * DD];
__device__ float          g_xbuf[2][NN * DD];
__device__ unsigned       g_adjbits[(size_t)NSTEPS * NN * NW];

__device__ __forceinline__ unsigned f2ord(float f) {
    unsigned u = __float_as_uint(f);
    return (u & 0x80000000u) ? ~u : (u | 0x80000000u);
}
__device__ __forceinline__ float ord2f(unsigned u) {
    u = (u & 0x80000000u) ? (u & 0x7FFFFFFFu) : ~u;
    return __uint_as_float(u);
}
#define ORD_NEG_INF 0x007FFFFFu

#define MMA16816(d, a, b) \
    asm volatile("mma.sync.aligned.m16n8k16.row.col.f32.bf16.bf16.f32 " \
                 "{%0,%1,%2,%3}, {%4,%5,%6,%7}, {%8,%9}, {%0,%1,%2,%3};" \
                 : "+f"((d)[0]), "+f"((d)[1]), "+f"((d)[2]), "+f"((d)[3]) \
                 : "r"((a)[0]), "r"((a)[1]), "r"((a)[2]), "r"((a)[3]), \
                   "r"((b)[0]), "r"((b)[1]))

__device__ __forceinline__ uint32_t pack_bf2(float a, float b) {
    __nv_bfloat16 ba = __float2bfloat16(a), bb = __float2bfloat16(b);
    return (uint32_t)__bfloat16_as_ushort(ba) |
           ((uint32_t)__bfloat16_as_ushort(bb) << 16);
}

// ---------------- pack adjacency bits (all steps, once) ----------------
__global__ void k_pack(const int* __restrict__ adj) {
    int lane = threadIdx.x & 31;
    size_t gw = (size_t)blockIdx.x * (blockDim.x >> 5) + (threadIdx.x >> 5);
    size_t nWtot = (size_t)NSTEPS * NN * NW;
    size_t stride = (size_t)gridDim.x * (blockDim.x >> 5);
    for (size_t w = gw; w < nWtot; w += stride) {
        int v = adj[w * 32 + lane];
        unsigned m = __ballot_sync(0xffffffffu, v > 0);
        if (lane == 0) g_adjbits[w] = m;
    }
}

// ---------------- per-step init ----------------
__global__ void k_init(int step, float* dout) {
    float* nxt = (step == NSTEPS - 1) ? dout : g_xbuf[step & 1];
    int i = blockIdx.x * blockDim.x + threadIdx.x;
    if (i < NN * DD) nxt[i] = 0.f;
    if (i < HH * NN) g_rowmax[i] = ORD_NEG_INF;
    if (i < HH * DD) g_hmean[i] = 0.f;
}

// ---------------- projection + normalize + bf16 splits + column mean ----------------
__global__ void k_project(int step, const float* __restrict__ feat,
                          const float* __restrict__ Ws) {
    const float* x = (step == 0) ? feat : g_xbuf[(step + 1) & 1];
    int h = blockIdx.y;
    const float* W = Ws + ((size_t)step * HH + h) * DD * DD;
    int row0 = blockIdx.x * 64;

    __shared__ float sW[DD * DD];
    __shared__ float sX[64 * DD];
    __shared__ float sPart[8][16];

    for (int i = threadIdx.x; i < DD * DD; i += 256) sW[i] = W[i];
    for (int i = threadIdx.x; i < 64 * DD; i += 256) sX[i] = x[(size_t)row0 * DD + i];
    __syncthreads();

    int tx = threadIdx.x & 63;
    int ty = threadIdx.x >> 6;

    float hv[16];
    #pragma unroll
    for (int i = 0; i < 16; i++) {
        int r = ty + i * 4;
        float acc = 0.f;
        #pragma unroll
        for (int d = 0; d < DD; d++) acc = fmaf(sX[r * DD + d], sW[d * DD + tx], acc);
        hv[i] = acc;
    }

    float ss[16];
    #pragma unroll
    for (int i = 0; i < 16; i++) ss[i] = hv[i] * hv[i];
    #pragma unroll
    for (int o = 16; o > 0; o >>= 1) {
        #pragma unroll
        for (int i = 0; i < 16; i++) ss[i] += __shfl_xor_sync(0xffffffffu, ss[i], o);
    }
    int w = threadIdx.x >> 5;
    if ((threadIdx.x & 31) == 0) {
        #pragma unroll
        for (int i = 0; i < 16; i++) sPart[w][i] = ss[i];
    }
    __syncthreads();

    float msum = 0.f;
    #pragma unroll
    for (int i = 0; i < 16; i++) {
        int r = ty + i * 4;
        float nsq = sPart[ty * 2][i] + sPart[ty * 2 + 1][i];
        float rn = 1.f / (sqrtf(nsq) + 1e-12f);
        size_t idx = ((size_t)h * NN + row0 + r) * DD + tx;
        float hnv = hv[i] * rn;
        __nv_bfloat16 nh = __float2bfloat16(hnv);
        g_hnhi[idx] = nh;
        g_hnlo[idx] = __float2bfloat16(hnv - __bfloat162float(nh));
        __nv_bfloat16 bh = __float2bfloat16(hv[i]);
        g_hbhi[idx] = bh;
        g_hblo[idx] = __float2bfloat16(hv[i] - __bfloat162float(bh));
        msum += hv[i];
    }
    atomicAdd(&g_hmean[h * DD + tx], msum * (1.0f / NN));
}

// ---------------- rowmax only: sim tiles via mma.sync, NO sim store ----------------
// grid (528, HH): upper-triangular 128x128 tile pairs. block 256 (8 warps: wm=warp&3
// rows wm*32..+31, wn=warp>>2 cols wn*64..+63). K=64, 4 k-tiles of 16.
#define SIMPAD 72
#define SIM_SMEM (4 * 128 * SIMPAD * 2)
__global__ void __launch_bounds__(256) k_sim(int step) {
    extern __shared__ char smc[];
    uint16_t* sAhi = (uint16_t*)smc;
    uint16_t* sAlo = sAhi + 128 * SIMPAD;
    uint16_t* sBhi = sAlo + 128 * SIMPAD;
    uint16_t* sBlo = sBhi + 128 * SIMPAD;
    int h = blockIdx.y;
    int tid = threadIdx.x;

    int idx0 = blockIdx.x, bi = 0;
    while (idx0 >= 32 - bi) { idx0 -= 32 - bi; bi++; }
    int bj = bi + idx0;
    int rb = bi * 128, cb = bj * 128;

    const __nv_bfloat16* Ah = g_hnhi + ((size_t)h * NN + rb) * DD;
    const __nv_bfloat16* Al = g_hnlo + ((size_t)h * NN + rb) * DD;
    const __nv_bfloat16* Bh = g_hnhi + ((size_t)h * NN + cb) * DD;
    const __nv_bfloat16* Bl = g_hnlo + ((size_t)h * NN + cb) * DD;
    #pragma unroll
    for (int t = 0; t < 8; t++) {
        int i2 = tid + t * 256;            // 2048 uint2 slots: 128 rows x 16
        int r = i2 >> 4, c = i2 & 15;
        size_t go = (size_t)r * DD + c * 4;
        *(uint2*)&sAhi[r * SIMPAD + c * 4] = *(const uint2*)(Ah + go);
        *(uint2*)&sAlo[r * SIMPAD + c * 4] = *(const uint2*)(Al + go);
        *(uint2*)&sBhi[r * SIMPAD + c * 4] = *(const uint2*)(Bh + go);
        *(uint2*)&sBlo[r * SIMPAD + c * 4] = *(const uint2*)(Bl + go);
    }
    __syncthreads();

    int warp = tid >> 5, lane = tid & 31;
    int wm = warp & 3, wn = warp >> 2;
    int q = lane >> 2, t4 = lane & 3;

    float d[2][8][4];
    #pragma unroll
    for (int mi = 0; mi < 2; mi++)
        #pragma unroll
        for (int nj = 0; nj < 8; nj++)
            #pragma unroll
            for (int p = 0; p < 4; p++) d[mi][nj][p] = 0.f;

    #pragma unroll
    for (int kt = 0; kt < 4; kt++) {
        int kk = kt * 16 + t4 * 2;
        uint32_t ahi[2][4], alo[2][4];
        #pragma unroll
        for (int mi = 0; mi < 2; mi++) {
            int r = wm * 32 + mi * 16 + q;
            ahi[mi][0] = *(const uint32_t*)&sAhi[(r + 0) * SIMPAD + kk];
            ahi[mi][1] = *(const uint32_t*)&sAhi[(r + 8) * SIMPAD + kk];
            ahi[mi][2] = *(const uint32_t*)&sAhi[(r + 0) * SIMPAD + kk + 8];
            ahi[mi][3] = *(const uint32_t*)&sAhi[(r + 8) * SIMPAD + kk + 8];
            alo[mi][0] = *(const uint32_t*)&sAlo[(r + 0) * SIMPAD + kk];
            alo[mi][1] = *(const uint32_t*)&sAlo[(r + 8) * SIMPAD + kk];
            alo[mi][2] = *(const uint32_t*)&sAlo[(r + 0) * SIMPAD + kk + 8];
            alo[mi][3] = *(const uint32_t*)&sAlo[(r + 8) * SIMPAD + kk + 8];
        }
        #pragma unroll
        for (int nj = 0; nj < 8; nj++) {
            int nr = wn * 64 + nj * 8 + q;
            uint32_t bh[2], bl[2];
            bh[0] = *(const uint32_t*)&sBhi[nr * SIMPAD + kk];
            bh[1] = *(const uint32_t*)&sBhi[nr * SIMPAD + kk + 8];
            bl[0] = *(const uint32_t*)&sBlo[nr * SIMPAD + kk];
            bl[1] = *(const uint32_t*)&sBlo[nr * SIMPAD + kk + 8];
            #pragma unroll
            for (int mi = 0; mi < 2; mi++) {
                MMA16816(d[mi][nj], ahi[mi], bh);
                MMA16816(d[mi][nj], ahi[mi], bl);
                MMA16816(d[mi][nj], alo[mi], bh);
                MMA16816(d[mi][nj], alo[mi], bl);
            }
        }
    }

    // scale by 1/TEMP = 5 (same op/order as the attn recompute)
    #pragma unroll
    for (int mi = 0; mi < 2; mi++)
        #pragma unroll
        for (int nj = 0; nj < 8; nj++)
            #pragma unroll
            for (int p = 0; p < 4; p++) d[mi][nj][p] *= 5.f;

    const unsigned* bits = g_adjbits + (size_t)step * NN * NW;

    // row-side masked row max (rows rb.., cols cb..)
    int cw = (cb >> 5) + wn * 2;
    #pragma unroll
    for (int mi = 0; mi < 2; mi++) {
        #pragma unroll
        for (int half = 0; half < 2; half++) {
            int lr = wm * 32 + mi * 16 + q + half * 8;
            int gr = rb + lr;
            unsigned w0 = bits[(size_t)gr * NW + cw];
            unsigned w1 = bits[(size_t)gr * NW + cw + 1];
            float lm = -INFINITY;
            #pragma unroll
            for (int nj = 0; nj < 8; nj++) {
                unsigned w = (nj < 4) ? w0 : w1;
                int bit = (nj & 3) * 8 + t4 * 2;
                if ((w >> bit) & 1)       lm = fmaxf(lm, d[mi][nj][half * 2 + 0]);
                if ((w >> (bit + 1)) & 1) lm = fmaxf(lm, d[mi][nj][half * 2 + 1]);
            }
            lm = fmaxf(lm, __shfl_xor_sync(0xffffffffu, lm, 1));
            lm = fmaxf(lm, __shfl_xor_sync(0xffffffffu, lm, 2));
            if (t4 == 0) atomicMax(&g_rowmax[h * NN + gr], f2ord(lm));
        }
    }

    // mirror: column-side masked max (rows cb+c, cols rb+..), register reduction
    if (bi != bj) {
        #pragma unroll
        for (int nj = 0; nj < 8; nj++) {
            #pragma unroll
            for (int jc = 0; jc < 2; jc++) {
                int c = wn * 64 + nj * 8 + t4 * 2 + jc;
                int gc = cb + c;
                unsigned w = bits[(size_t)gc * NW + (rb >> 5) + wm];
                float lm = -INFINITY;
                #pragma unroll
                for (int mi = 0; mi < 2; mi++)
                    #pragma unroll
                    for (int half = 0; half < 2; half++) {
                        int bit = mi * 16 + q + half * 8;
                        if ((w >> bit) & 1) lm = fmaxf(lm, d[mi][nj][half * 2 + jc]);
                    }
                lm = fmaxf(lm, __shfl_xor_sync(0xffffffffu, lm, 4));
                lm = fmaxf(lm, __shfl_xor_sync(0xffffffffu, lm, 8));
                lm = fmaxf(lm, __shfl_xor_sync(0xffffffffu, lm, 16));
                if (q == 0) atomicMax(&g_rowmax[h * NN + gc], f2ord(lm));
            }
        }
    }
}

// ---------------- fused: recompute sim tile (MMA) + keep/exp + P@h (MMA) ----------------
// grid (NN/32, HH). block 256 (8 warps). 32 sim-rows per block; cb loop over 128-col tiles.
// sim-MMA warp map: mh=warp&1 (rows mh*16), nq=warp>>1 (cols nq*32; nj 0..3 n8-tiles).
// P@h warp map (R15): mh rows, nq -> out cols nq*16 (nt 0..1).
#define SPAD 136
#define TPAD 138
#define ATTN_SMEM ((32*SIMPAD*2 + 128*SIMPAD*2 + 32*SPAD*2 + 64*TPAD*2) * 2 + 256)
__global__ void __launch_bounds__(256) k_attn(int step, float* __restrict__ doutp) {
    extern __shared__ char smc[];
    uint16_t* sAhi = (uint16_t*)smc;                  // [32][72]  hn rows rb..
    uint16_t* sAlo = sAhi + 32 * SIMPAD;
    uint16_t* sNhi = sAlo + 32 * SIMPAD;              // [128][72] hn rows cb..
    uint16_t* sNlo = sNhi + 128 * SIMPAD;
    uint16_t* sPhi = sNlo + 128 * SIMPAD;             // [32][136] P tile
    uint16_t* sPlo = sPhi + 32 * SPAD;
    uint16_t* sThi = sPlo + 32 * SPAD;                // [64][138] h^T tile
    uint16_t* sTlo = sThi + 64 * TPAD;
    float*    sRM  = (float*)(sTlo + 64 * TPAD);
    float*    sDen = sRM + 32;

    float* out = (step == NSTEPS - 1) ? doutp : g_xbuf[step & 1];
    int h = blockIdx.y;
    int rb = blockIdx.x * 32;
    int tid = threadIdx.x;
    int warp = tid >> 5, lane = tid & 31;
    const int mh = warp & 1, nq = warp >> 1;
    const int q = lane >> 2, t4 = lane & 3;

    if (tid < 32) {
        sRM[tid] = ord2f(g_rowmax[h * NN + rb + tid]);
        sDen[tid] = 0.f;
    }
    // A-side hn rows rb..rb+31 (loaded once)
    {
        const __nv_bfloat16* Ah = g_hnhi + ((size_t)h * NN + rb) * DD;
        const __nv_bfloat16* Al = g_hnlo + ((size_t)h * NN + rb) * DD;
        #pragma unroll
        for (int t = 0; t < 2; t++) {
            int i2 = tid + t * 256;        // 512 uint2 slots: 32 rows x 16
            int r = i2 >> 4, c = i2 & 15;
            size_t go = (size_t)r * DD + c * 4;
            *(uint2*)&sAhi[r * SIMPAD + c * 4] = *(const uint2*)(Ah + go);
            *(uint2*)&sAlo[r * SIMPAD + c * 4] = *(const uint2*)(Al + go);
        }
    }

    float acc[2][4];
    #pragma unroll
    for (int i = 0; i < 2; i++)
        #pragma unroll
        for (int j = 0; j < 4; j++) acc[i][j] = 0.f;

    const __nv_bfloat16* hnh = g_hnhi + (size_t)h * NN * DD;
    const __nv_bfloat16* hnl = g_hnlo + (size_t)h * NN * DD;
    const __nv_bfloat16* hbh = g_hbhi + (size_t)h * NN * DD;
    const __nv_bfloat16* hbl = g_hblo + (size_t)h * NN * DD;
    const unsigned* adjb = g_adjbits + (size_t)step * NN * NW;

    for (int cb = 0; cb < NN; cb += 128) {
        __syncthreads();
        // B-side hn rows cb..cb+127 (for sim recompute)
        #pragma unroll
        for (int t = 0; t < 8; t++) {
            int i2 = tid + t * 256;        // 2048 uint2 slots
            int r = i2 >> 4, c = i2 & 15;
            size_t go = (size_t)(cb + r) * DD + c * 4;
            *(uint2*)&sNhi[r * SIMPAD + c * 4] = *(const uint2*)(hnh + go);
            *(uint2*)&sNlo[r * SIMPAD + c * 4] = *(const uint2*)(hnl + go);
        }
        // h^T tile for P@h
        #pragma unroll
        for (int t = 0; t < 16; t++) {
            int i2 = tid + t * 256;
            int cc = i2 >> 5;
            int ep = (i2 & 31) * 2;
            uint32_t vh = *(const uint32_t*)&hbh[(size_t)(cb + cc) * DD + ep];
            uint32_t vl = *(const uint32_t*)&hbl[(size_t)(cb + cc) * DD + ep];
            sThi[(ep + 0) * TPAD + cc] = (uint16_t)(vh & 0xffffu);
            sThi[(ep + 1) * TPAD + cc] = (uint16_t)(vh >> 16);
            sTlo[(ep + 0) * TPAD + cc] = (uint16_t)(vl & 0xffffu);
            sTlo[(ep + 1) * TPAD + cc] = (uint16_t)(vl >> 16);
        }
        __syncthreads();

        // ---- sim recompute: 32x128 tile; warp computes rows mh*16.., cols nq*32.. ----
        float ds[4][4];
        #pragma unroll
        for (int nj = 0; nj < 4; nj++)
            #pragma unroll
            for (int p = 0; p < 4; p++) ds[nj][p] = 0.f;

        #pragma unroll
        for (int kt = 0; kt < 4; kt++) {
            int kk = kt * 16 + t4 * 2;
            uint32_t ahi[4], alo[4];
            int r = mh * 16 + q;
            ahi[0] = *(const uint32_t*)&sAhi[(r + 0) * SIMPAD + kk];
            ahi[1] = *(const uint32_t*)&sAhi[(r + 8) * SIMPAD + kk];
            ahi[2] = *(const uint32_t*)&sAhi[(r + 0) * SIMPAD + kk + 8];
            ahi[3] = *(const uint32_t*)&sAhi[(r + 8) * SIMPAD + kk + 8];
            alo[0] = *(const uint32_t*)&sAlo[(r + 0) * SIMPAD + kk];
            alo[1] = *(const uint32_t*)&sAlo[(r + 8) * SIMPAD + kk];
            alo[2] = *(const uint32_t*)&sAlo[(r + 0) * SIMPAD + kk + 8];
            alo[3] = *(const uint32_t*)&sAlo[(r + 8) * SIMPAD + kk + 8];
            #pragma unroll
            for (int nj = 0; nj < 4; nj++) {
                int nr = nq * 32 + nj * 8 + q;
                uint32_t bh[2], bl[2];
                bh[0] = *(const uint32_t*)&sNhi[nr * SIMPAD + kk];
                bh[1] = *(const uint32_t*)&sNhi[nr * SIMPAD + kk + 8];
                bl[0] = *(const uint32_t*)&sNlo[nr * SIMPAD + kk];
                bl[1] = *(const uint32_t*)&sNlo[nr * SIMPAD + kk + 8];
                MMA16816(ds[nj], ahi, bh);
                MMA16816(ds[nj], ahi, bl);
                MMA16816(ds[nj], alo, bh);
                MMA16816(ds[nj], alo, bl);
            }
        }

        // ---- keep + exp + pack into sP; denominator partials ----
        unsigned mword0 = adjb[(size_t)(rb + mh * 16 + q) * NW + (cb >> 5) + nq];
        unsigned mword1 = adjb[(size_t)(rb + mh * 16 + q + 8) * NW + (cb >> 5) + nq];
        float den0 = 0.f, den1 = 0.f;
        float rm0 = sRM[mh * 16 + q], rm1 = sRM[mh * 16 + q + 8];
        float th0 = 0.5f * rm0, th1 = 0.5f * rm1;
        #pragma unroll
        for (int nj = 0; nj < 4; nj++) {
            int bit = nj * 8 + t4 * 2;
            float s00 = ds[nj][0] * 5.f, s01 = ds[nj][1] * 5.f;
            float s10 = ds[nj][2] * 5.f, s11 = ds[nj][3] * 5.f;
            float p00 = (((mword0 >> (bit + 0)) & 1) && s00 >= th0) ? __expf(s00 - rm0) : 0.f;
            float p01 = (((mword0 >> (bit + 1)) & 1) && s01 >= th0) ? __expf(s01 - rm0) : 0.f;
            float p10 = (((mword1 >> (bit + 0)) & 1) && s10 >= th1) ? __expf(s10 - rm1) : 0.f;
            float p11 = (((mword1 >> (bit + 1)) & 1) && s11 >= th1) ? __expf(s11 - rm1) : 0.f;
            den0 += p00 + p01;
            den1 += p10 + p11;
            int col = nq * 32 + nj * 8 + t4 * 2;
            float h00 = __bfloat162float(__float2bfloat16(p00));
            float h01 = __bfloat162float(__float2bfloat16(p01));
            float h10 = __bfloat162float(__float2bfloat16(p10));
            float h11 = __bfloat162float(__float2bfloat16(p11));
            *(uint32_t*)&sPhi[(mh * 16 + q + 0) * SPAD + col] = pack_bf2(p00, p01);
            *(uint32_t*)&sPhi[(mh * 16 + q + 8) * SPAD + col] = pack_bf2(p10, p11);
            *(uint32_t*)&sPlo[(mh * 16 + q + 0) * SPAD + col] = pack_bf2(p00 - h00, p01 - h01);
            *(uint32_t*)&sPlo[(mh * 16 + q + 8) * SPAD + col] = pack_bf2(p10 - h10, p11 - h11);
        }
        den0 += __shfl_xor_sync(0xffffffffu, den0, 1);
        den0 += __shfl_xor_sync(0xffffffffu, den0, 2);
        den1 += __shfl_xor_sync(0xffffffffu, den1, 1);
        den1 += __shfl_xor_sync(0xffffffffu, den1, 2);
        if (t4 == 0) {
            atomicAdd(&sDen[mh * 16 + q], den0);
            atomicAdd(&sDen[mh * 16 + q + 8], den1);
        }
        __syncthreads();

        // ---- P@h MMA (R15, 4 terms) ----
        const int ar = mh * 16 + q;
        #pragma unroll 2
        for (int kt = 0; kt < 8; kt++) {
            int k0 = kt * 16 + t4 * 2;
            uint32_t ahi[4], alo[4];
            ahi[0] = *(const uint32_t*)&sPhi[(ar + 0) * SPAD + k0];
            ahi[1] = *(const uint32_t*)&sPhi[(ar + 8) * SPAD + k0];
            ahi[2] = *(const uint32_t*)&sPhi[(ar + 0) * SPAD + k0 + 8];
            ahi[3] = *(const uint32_t*)&sPhi[(ar + 8) * SPAD + k0 + 8];
            alo[0] = *(const uint32_t*)&sPlo[(ar + 0) * SPAD + k0];
            alo[1] = *(const uint32_t*)&sPlo[(ar + 8) * SPAD + k0];
            alo[2] = *(const uint32_t*)&sPlo[(ar + 0) * SPAD + k0 + 8];
            alo[3] = *(const uint32_t*)&sPlo[(ar + 8) * SPAD + k0 + 8];
            #pragma unroll
            for (int nt = 0; nt < 2; nt++) {
                int n0 = nq * 16 + nt * 8 + q;
                uint32_t bh[2], bl[2];
                bh[0] = *(const uint32_t*)&sThi[n0 * TPAD + k0];
                bh[1] = *(const uint32_t*)&sThi[n0 * TPAD + k0 + 8];
                bl[0] = *(const uint32_t*)&sTlo[n0 * TPAD + k0];
                bl[1] = *(const uint32_t*)&sTlo[n0 * TPAD + k0 + 8];
                MMA16816(acc[nt], ahi, bh);
                MMA16816(acc[nt], ahi, bl);
                MMA16816(acc[nt], alo, bh);
                MMA16816(acc[nt], alo, bl);
            }
        }
    }
    __syncthreads();

    #pragma unroll
    for (int nt = 0; nt < 2; nt++) {
        #pragma unroll
        for (int half = 0; half < 2; half++) {
            int lr = mh * 16 + q + half * 8;
            int r = rb + lr;
            float den = sDen[lr];
            float inv = (den > 0.f) ? (1.f / den) : 0.f;
            #pragma unroll
            for (int j = 0; j < 2; j++) {
                int e = nq * 16 + nt * 8 + t4 * 2 + j;
                float a = acc[nt][half * 2 + j];
                float v = (den > 0.f) ? (a * inv) : g_hmean[h * DD + e];
                v = (v > 0.f) ? v : (expf(v) - 1.f);   // elu
                atomicAdd(&out[(size_t)r * DD + e], 0.25f * v);
            }
        }
    }
}

// ---------------- launch ----------------
extern "C" void kernel_launch(void* const* d_in, const int* in_sizes, int n_in,
                              void* d_out, int out_size) {
    const float* feat = (const float*)d_in[0];
    const int*   adj  = (const int*)d_in[1];
    const float* Ws   = (const float*)d_in[2];
    float* out = (float*)d_out;

    cudaFuncSetAttribute(k_sim,  cudaFuncAttributeMaxDynamicSharedMemorySize, SIM_SMEM);
    cudaFuncSetAttribute(k_attn, cudaFuncAttributeMaxDynamicSharedMemorySize, ATTN_SMEM);

    k_pack<<<2048, 256>>>(adj);
    for (int s = 0; s < NSTEPS; s++) {
        k_init<<<1024, 256>>>(s, out);
        k_project<<<dim3(NN / 64, HH), 256>>>(s, feat, Ws);
        k_sim<<<dim3(528, HH), 256, SIM_SMEM>>>(s);
        k_attn<<<dim3(NN / 32, HH), 256, ATTN_SMEM>>>(s, out);
    }
}